// round 13
// baseline (speedup 1.0000x reference)
#include <cuda_runtime.h>
#include <cuda_pipeline.h>
#include <math.h>

// Dihedral angle over 4 carbon atoms (indices 0,4,7,11 of 14) for B molecules.
// x: [B, 42] float32, out: [B] float32.
//
// R13: warp-autonomous double-buffered pipelines. cp.async group state is
// per-thread, so each warp runs its own 32-row tile pipeline with only
// __syncwarp — no CTA barriers, no cross-warp coupling. 4 warps/CTA,
// 2x5376B buffers per warp = 43KB smem -> 5 CTAs/SM = 20 independent
// pipelines/SM. Full-row contiguous streaming (sector-optimal; R10 proved
// gathering loses, R11 proved depth/engine don't matter past the ceiling).

constexpr int WTILE       = 32;                   // rows per warp-tile
constexpr int WARPS       = 4;
constexpr int THREADS     = WARPS * 32;
constexpr int FPR         = 42;                   // floats per row
constexpr int WT_FLOATS   = WTILE * FPR;          // 1344
constexpr int WT_F4       = WT_FLOATS / 4;        // 336 (exact)
constexpr int CTAS_PER_SM = 5;

__global__ __launch_bounds__(THREADS, CTAS_PER_SM)
void dihedral_kernel(const float* __restrict__ x,
                     float* __restrict__ out,
                     int B, int nWTiles)
{
    // [warp][buf][floats]  : 4 * 2 * 5376B = 43008 B
    __shared__ alignas(16) float sbuf[WARPS][2][WT_FLOATS];

    const int warp = threadIdx.x >> 5;
    const int lane = threadIdx.x & 31;
    const int wstride = (int)gridDim.x * WARPS;        // total warp pipelines
    const int g0 = blockIdx.x * WARPS + warp;          // this warp's first tile

    // Stage warp-tile t into this warp's buffer `buf` (per-thread cp.async).
    auto issue = [&](int t, int buf) {
        if (t < nWTiles) {
            const int rows   = min(WTILE, B - t * WTILE);
            const int total4 = (rows * FPR) >> 2;      // rows*42 always even
            // base byte offset = t*5376 -> 16B aligned
            const float4* __restrict__ s4 =
                reinterpret_cast<const float4*>(x + (size_t)t * WT_FLOATS);
            float4* d4 = reinterpret_cast<float4*>(sbuf[warp][buf]);
            #pragma unroll 11
            for (int i = lane; i < total4; i += 32)
                __pipeline_memcpy_async(&d4[i], &s4[i], 16);
            const int rem = (rows * FPR) & 3;          // 0 or 2
            if (lane < rem) {
                int i = (total4 << 2) + lane;
                __pipeline_memcpy_async(&sbuf[warp][buf][i],
                                        &x[(size_t)t * WT_FLOATS + i], 4);
            }
        }
        __pipeline_commit();   // uniform per-thread group counting
    };

    int buf = 0;
    issue(g0, buf);                                    // prologue

    for (int t = g0; t < nWTiles; t += wstride) {
        issue(t + wstride, buf ^ 1);                   // prefetch next

        __pipeline_wait_prior(1);                      // current tile landed
        __syncwarp();                                  // visible warp-wide

        const int rows = min(WTILE, B - t * WTILE);
        if (lane < rows) {
            const float* row = sbuf[warp][buf] + lane * FPR;

            // Carbon atoms 0,4,7,11 -> float offsets 0,12,21,33
            float c0x = row[0],  c0y = row[1],  c0z = row[2];
            float c1x = row[12], c1y = row[13], c1z = row[14];
            float c2x = row[21], c2y = row[22], c2z = row[23];
            float c3x = row[33], c3y = row[34], c3z = row[35];

            float v0x = c1x - c0x, v0y = c1y - c0y, v0z = c1z - c0z;
            float v1x = c2x - c1x, v1y = c2y - c1y, v1z = c2z - c1z;
            float v2x = c3x - c2x, v2y = c3y - c2y, v2z = c3z - c2z;

            // na = cross(-v0, v1)
            float nax = -(v0y * v1z - v0z * v1y);
            float nay = -(v0z * v1x - v0x * v1z);
            float naz = -(v0x * v1y - v0y * v1x);

            // nb = cross(-v1, v2)
            float nbx = -(v1y * v2z - v1z * v2y);
            float nby = -(v1z * v2x - v1x * v2z);
            float nbz = -(v1x * v2y - v1y * v2x);

            float xx = nax * nbx + nay * nby + naz * nbz;

            // xp = cross(na, nb)
            float xpx = nay * nbz - naz * nby;
            float xpy = naz * nbx - nax * nbz;
            float xpz = nax * nby - nay * nbx;

            float inv_n1 = rsqrtf(v1x * v1x + v1y * v1y + v1z * v1z);
            float yy = (v1x * xpx + v1y * xpy + v1z * xpz) * inv_n1;

            out[t * WTILE + lane] = atan2f(yy, xx);
        }
        __syncwarp();       // all lanes done reading before buffer refill
        buf ^= 1;
    }
}

extern "C" void kernel_launch(void* const* d_in, const int* in_sizes, int n_in,
                              void* d_out, int out_size)
{
    // Identify x (the big input) vs mask_matrix (56 elements, constant).
    int xi = 0;
    for (int i = 1; i < n_in; i++)
        if (in_sizes[i] > in_sizes[xi]) xi = i;

    const float* x = (const float*)d_in[xi];
    float* out = (float*)d_out;
    const int B = in_sizes[xi] / FPR;                  // 2,000,000
    const int nWTiles = (B + WTILE - 1) / WTILE;       // 62500

    const int grid = 148 * CTAS_PER_SM;                // 740: one full wave
    dihedral_kernel<<<grid, THREADS>>>(x, out, B, nWTiles);
}